// round 15
// baseline (speedup 1.0000x reference)
#include <cuda_runtime.h>

#define B_   16
#define L_   480000
#define D_   9
#define NP1  30000     // level-1 (16-sample rows)
#define NQ2  1875      // level-2
#define NU3  118       // level-3 (1875 padded to 1888)
#define NV4  8         // level-4 (118 padded to 128)

__device__ float g_e1[B_ * D_ * NP1];
__device__ float g_S2[B_ * D_ * NQ2];
__device__ float g_S1[B_ * D_ * NP1];

// rad = fl( fl(f*h) * fl(1/24000) )  [XLA algsimp HandleDivide: A/c -> A*(1/c)]
#define RECIP_SR ((float)(1.0 / 24000.0))
__device__ __forceinline__ float rad_of(float f, float hd) {
    return __fmul_rn(__fmul_rn(f, hd), RECIP_SR);
}

__device__ __forceinline__ void load16(const float4* p, float x[16]) {
#pragma unroll
    for (int i = 0; i < 4; i++) {
        float4 v = p[i];
        x[4*i] = v.x; x[4*i+1] = v.y; x[4*i+2] = v.z; x[4*i+3] = v.w;
    }
}

// ---- kA: e1[p] = Seq16 of rads (rand_ini folded into element 0) ----
__global__ void __launch_bounds__(256) kA(const float* __restrict__ f0,
                                          const float* __restrict__ rnd) {
    int tid = blockIdx.x * 256 + threadIdx.x;
    if (tid >= B_ * NP1) return;
    int b = tid / NP1, p = tid - b * NP1;
    float f[16];
    load16((const float4*)(f0 + (size_t)b * L_ + (size_t)p * 16), f);
#pragma unroll
    for (int d = 0; d < D_; d++) {
        float hd = (float)(d + 1);
        float acc = 0.f;
#pragma unroll
        for (int j = 0; j < 16; j++) {
            float rad = rad_of(f[j], hd);
            if (p == 0 && j == 0) rad = __fadd_rn(rad, rnd[b * D_ + d]);
            acc = j ? __fadd_rn(acc, rad) : rad;
        }
        g_e1[(size_t)(b * D_ + d) * NP1 + p] = acc;
    }
}

// ---- kB: per (b,d) row -> S2 via e2,e3,e4,S4,S3 (all sequential) ----
__global__ void __launch_bounds__(512) kB() {
    __shared__ float e2[NQ2], e3[NU3], S3[NU3], S4[NV4];
    int row = blockIdx.x, t = threadIdx.x;
    const float* e1 = g_e1 + (size_t)row * NP1;
    for (int q = t; q < NQ2; q += 512) {
        float x[16];
        load16((const float4*)(e1 + q * 16), x);
        float acc = x[0];
#pragma unroll
        for (int j = 1; j < 16; j++) acc = __fadd_rn(acc, x[j]);
        e2[q] = acc;
    }
    __syncthreads();
    for (int u = t; u < NU3; u += 512) {
        int n = min(16, NQ2 - u * 16);
        float acc = 0.f;
        for (int j = 0; j < n; j++) {
            float v = e2[u * 16 + j];
            acc = j ? __fadd_rn(acc, v) : v;
        }
        e3[u] = acc;
    }
    __syncthreads();
    if (t == 0) {
        float e4[NV4];
        for (int v = 0; v < NV4; v++) {
            int n = min(16, NU3 - v * 16);
            float acc = 0.f;
            for (int j = 0; j < n; j++) {
                float x = e3[v * 16 + j];
                acc = j ? __fadd_rn(acc, x) : x;
            }
            e4[v] = acc;
        }
        float s = 0.f;
        for (int v = 0; v < NV4; v++) {
            s = v ? __fadd_rn(s, e4[v]) : e4[v];
            S4[v] = s;
        }
    }
    __syncthreads();
    for (int u = t; u < NU3; u += 512) {
        int base = (u >> 4) * 16;
        float off = (u >= 16) ? S4[(u >> 4) - 1] : 0.f;
        float acc = 0.f;
        for (int j = base; j <= u; j++)
            acc = (j == base) ? e3[j] : __fadd_rn(acc, e3[j]);
        S3[u] = __fadd_rn(off, acc);
    }
    __syncthreads();
    float* S2 = g_S2 + (size_t)row * NQ2;
    for (int q = t; q < NQ2; q += 512) {
        int base = (q >> 4) * 16;
        float off = (q >= 16) ? S3[(q >> 4) - 1] : 0.f;
        float acc = 0.f;
        for (int j = base; j <= q; j++)
            acc = (j == base) ? e2[j] : __fadd_rn(acc, e2[j]);
        S2[q] = __fadd_rn(off, acc);
    }
}

// ---- kB2: S1[p] = fadd(S2[q-1], seq-chain of e1 within 16-chunk) ----
__global__ void __launch_bounds__(256) kB2() {
    int tid = blockIdx.x * 256 + threadIdx.x;
    if (tid >= B_ * D_ * NQ2) return;
    int row = tid / NQ2, q = tid - row * NQ2;
    float off = q ? g_S2[(size_t)row * NQ2 + q - 1] : 0.f;
    float x[16];
    load16((const float4*)(g_e1 + (size_t)row * NP1 + (size_t)q * 16), x);
    float s[16];
    float acc = 0.f;
#pragma unroll
    for (int j = 0; j < 16; j++) {
        acc = j ? __fadd_rn(acc, x[j]) : x[j];
        s[j] = __fadd_rn(off, acc);
    }
    float4* o = (float4*)(g_S1 + (size_t)row * NP1 + (size_t)q * 16);
#pragma unroll
    for (int i = 0; i < 4; i++)
        o[i] = make_float4(s[4*i], s[4*i+1], s[4*i+2], s[4*i+3]);
}

__device__ __forceinline__ float sin_ph2(float s, float ph) {
    float k = rintf(s);                                  // valid reduction integer
    float r = __fmaf_rn(k, -6.28318548202514648f, ph);
    r       = __fmaf_rn(k, 1.7484556e-07f, r);
    return __sinf(r);
}

// one quarter of a row: recompute exact J0-prefix fold, emit samples J0..J0+3
template<int J0>
__device__ __forceinline__ void row_quarter(
    const float* __restrict__ fptr, const float* __restrict__ rnd9,
    int r, int b, float* __restrict__ outPtr,
    float* __restrict__ upPtr, int writeU)
{
    constexpr int NF = J0 + 4;
    float f[NF];
#pragma unroll
    for (int i = 0; i < NF / 4; i++) {
        float4 v = ((const float4*)fptr)[i];
        f[4*i] = v.x; f[4*i+1] = v.y; f[4*i+2] = v.z; f[4*i+3] = v.w;
    }
    if (writeU) {
        ((float4*)upPtr)[J0 / 4] =
            make_float4(f[J0]>0.f?1.f:0.f, f[J0+1]>0.f?1.f:0.f,
                        f[J0+2]>0.f?1.f:0.f, f[J0+3]>0.f?1.f:0.f);
    }
    float off0[D_], add0[D_];
#pragma unroll
    for (int d = 0; d < D_; d++) {
        off0[d] = (r > 0) ? __ldg(&g_S1[(size_t)(b * D_ + d) * NP1 + (r - 1)]) : 0.f;
        add0[d] = (r == 0) ? rnd9[d] : 0.f;    // fadd(x,+0)=x bitwise for x>=0
    }
    float out36[36];
#pragma unroll
    for (int d = 0; d < D_; d++) {
        float hd = (float)(d + 1);
        float acc = 0.f;
#pragma unroll
        for (int j = 0; j < J0; j++) {         // exact prefix fold
            float rad = rad_of(f[j], hd);
            if (j == 0) rad = __fadd_rn(rad, add0[d]);
            acc = j ? __fadd_rn(acc, rad) : rad;
        }
#pragma unroll
        for (int j = J0; j < J0 + 4; j++) {
            float rad = rad_of(f[j], hd);
            if (j == 0) rad = __fadd_rn(rad, add0[d]);
            acc = j ? __fadd_rn(acc, rad) : rad;
            float s  = __fadd_rn(off0[d], acc);
            float ph = __fmul_rn(s, 6.28318548202514648f);
            float sv = sin_ph2(s, ph);
            out36[(j - J0) * 9 + d] = (f[j] > 0.f) ? __fmul_rn(sv, 0.1f) : 0.f;
        }
    }
    float4* og = (float4*)outPtr;
#pragma unroll
    for (int i = 0; i < 9; i++)
        og[i] = make_float4(out36[4*i], out36[4*i+1], out36[4*i+2], out36[4*i+3]);
}

// ---- kC: smem-free; 256 threads = 64 rows x 4 quarters; direct stores ----
__global__ void __launch_bounds__(256) kC(const float* __restrict__ f0,
                                          const float* __restrict__ rnd,
                                          float* __restrict__ outS,
                                          float* __restrict__ outU, int writeU) {
    int t = threadIdx.x;
    int qk = t >> 6;                       // warp-uniform quarter
    int rowg = blockIdx.x * 64 + (t & 63); // global row in [0, B_*NP1)
    int b = rowg / NP1, r = rowg - b * NP1;
    const float* fptr = f0 + (size_t)b * L_ + (size_t)r * 16;
    float* upPtr = outU + (size_t)b * L_ + (size_t)r * 16;
    const float* rnd9 = rnd + b * D_;
    float* outPtr = outS + ((size_t)b * L_ + (size_t)r * 16 + qk * 4) * D_;
    switch (qk) {
        case 0:  row_quarter<0>(fptr, rnd9, r, b, outPtr, upPtr, writeU); break;
        case 1:  row_quarter<4>(fptr, rnd9, r, b, outPtr, upPtr, writeU); break;
        case 2:  row_quarter<8>(fptr, rnd9, r, b, outPtr, upPtr, writeU); break;
        default: row_quarter<12>(fptr, rnd9, r, b, outPtr, upPtr, writeU); break;
    }
}

extern "C" void kernel_launch(void* const* d_in, const int* in_sizes, int n_in,
                              void* d_out, int out_size) {
    const float* f0  = (const float*)d_in[0];
    const float* rnd = (const float*)d_in[1];
    float* outS = (float*)d_out;
    float* outU = outS + (size_t)B_ * L_ * D_;
    int writeU = (out_size >= B_ * L_ * D_ + B_ * L_) ? 1 : 0;

    kA<<<(B_ * NP1 + 255) / 256, 256>>>(f0, rnd);
    kB<<<B_ * D_, 512>>>();
    kB2<<<(B_ * D_ * NQ2 + 255) / 256, 256>>>();
    kC<<<B_ * NP1 / 64, 256>>>(f0, rnd, outS, outU, writeU);
}

// round 16
// speedup vs baseline: 1.3853x; 1.3853x over previous
#include <cuda_runtime.h>

#define B_   16
#define L_   480000
#define D_   9
#define NP1  30000     // level-1 (16-sample rows)
#define NQ2  1875      // level-2
#define NU3  118       // level-3 (1875 padded to 1888)
#define NV4  8         // level-4 (118 padded to 128)
#define RPB  64
#define NBX  469       // ceil(30000/64)

__device__ float g_e1[B_ * D_ * NP1];
__device__ float g_S2[B_ * D_ * NQ2];
__device__ float g_S1[B_ * D_ * NP1];

// rad = fl( fl(f*h) * fl(1/24000) )  [XLA algsimp HandleDivide: A/c -> A*(1/c)]
#define RECIP_SR ((float)(1.0 / 24000.0))
__device__ __forceinline__ float rad_of(float f, float hd) {
    return __fmul_rn(__fmul_rn(f, hd), RECIP_SR);
}

__device__ __forceinline__ void load16(const float4* p, float x[16]) {
#pragma unroll
    for (int i = 0; i < 4; i++) {
        float4 v = p[i];
        x[4*i] = v.x; x[4*i+1] = v.y; x[4*i+2] = v.z; x[4*i+3] = v.w;
    }
}

// ---- kA: e1[p] = Seq16 of rads (rand_ini folded into element 0) ----
__global__ void __launch_bounds__(256) kA(const float* __restrict__ f0,
                                          const float* __restrict__ rnd) {
    int tid = blockIdx.x * 256 + threadIdx.x;
    if (tid >= B_ * NP1) return;
    int b = tid / NP1, p = tid - b * NP1;
    float f[16];
    load16((const float4*)(f0 + (size_t)b * L_ + (size_t)p * 16), f);
#pragma unroll
    for (int d = 0; d < D_; d++) {
        float hd = (float)(d + 1);
        float acc = 0.f;
#pragma unroll
        for (int j = 0; j < 16; j++) {
            float rad = rad_of(f[j], hd);
            if (p == 0 && j == 0) rad = __fadd_rn(rad, rnd[b * D_ + d]);
            acc = j ? __fadd_rn(acc, rad) : rad;
        }
        g_e1[(size_t)(b * D_ + d) * NP1 + p] = acc;
    }
}

// ---- kB: per (b,d) row -> S2 via e2,e3,e4,S4,S3 (all sequential) ----
__global__ void __launch_bounds__(512) kB() {
    __shared__ float e2[NQ2], e3[NU3], S3[NU3], S4[NV4];
    int row = blockIdx.x, t = threadIdx.x;
    const float* e1 = g_e1 + (size_t)row * NP1;
    for (int q = t; q < NQ2; q += 512) {
        float x[16];
        load16((const float4*)(e1 + q * 16), x);
        float acc = x[0];
#pragma unroll
        for (int j = 1; j < 16; j++) acc = __fadd_rn(acc, x[j]);
        e2[q] = acc;
    }
    __syncthreads();
    for (int u = t; u < NU3; u += 512) {
        int n = min(16, NQ2 - u * 16);
        float acc = 0.f;
        for (int j = 0; j < n; j++) {
            float v = e2[u * 16 + j];
            acc = j ? __fadd_rn(acc, v) : v;
        }
        e3[u] = acc;
    }
    __syncthreads();
    if (t == 0) {
        float e4[NV4];
        for (int v = 0; v < NV4; v++) {
            int n = min(16, NU3 - v * 16);
            float acc = 0.f;
            for (int j = 0; j < n; j++) {
                float x = e3[v * 16 + j];
                acc = j ? __fadd_rn(acc, x) : x;
            }
            e4[v] = acc;
        }
        float s = 0.f;
        for (int v = 0; v < NV4; v++) {
            s = v ? __fadd_rn(s, e4[v]) : e4[v];
            S4[v] = s;
        }
    }
    __syncthreads();
    for (int u = t; u < NU3; u += 512) {
        int base = (u >> 4) * 16;
        float off = (u >= 16) ? S4[(u >> 4) - 1] : 0.f;
        float acc = 0.f;
        for (int j = base; j <= u; j++)
            acc = (j == base) ? e3[j] : __fadd_rn(acc, e3[j]);
        S3[u] = __fadd_rn(off, acc);
    }
    __syncthreads();
    float* S2 = g_S2 + (size_t)row * NQ2;
    for (int q = t; q < NQ2; q += 512) {
        int base = (q >> 4) * 16;
        float off = (q >= 16) ? S3[(q >> 4) - 1] : 0.f;
        float acc = 0.f;
        for (int j = base; j <= q; j++)
            acc = (j == base) ? e2[j] : __fadd_rn(acc, e2[j]);
        S2[q] = __fadd_rn(off, acc);
    }
}

// ---- kB2: S1[p] = fadd(S2[q-1], seq-chain of e1 within 16-chunk) ----
__global__ void __launch_bounds__(256) kB2() {
    int tid = blockIdx.x * 256 + threadIdx.x;
    if (tid >= B_ * D_ * NQ2) return;
    int row = tid / NQ2, q = tid - row * NQ2;
    float off = q ? g_S2[(size_t)row * NQ2 + q - 1] : 0.f;
    float x[16];
    load16((const float4*)(g_e1 + (size_t)row * NP1 + (size_t)q * 16), x);
    float s[16];
    float acc = 0.f;
#pragma unroll
    for (int j = 0; j < 16; j++) {
        acc = j ? __fadd_rn(acc, x[j]) : x[j];
        s[j] = __fadd_rn(off, acc);
    }
    float4* o = (float4*)(g_S1 + (size_t)row * NP1 + (size_t)q * 16);
#pragma unroll
    for (int i = 0; i < 4; i++)
        o[i] = make_float4(s[4*i], s[4*i+1], s[4*i+2], s[4*i+3]);
}

__device__ __forceinline__ float sin_ph2(float s, float ph) {
    float k = rintf(s);                                  // valid reduction integer
    float r = __fmaf_rn(k, -6.28318548202514648f, ph);
    r       = __fmaf_rn(k, 1.7484556e-07f, r);
    return __sinf(r);
}

// one quarter of a row: recompute exact J0-prefix fold, emit samples J0..J0+3
template<int J0>
__device__ __forceinline__ void row_quarter(
    const float* __restrict__ fptr, const float* __restrict__ rnd9,
    int r, int tr, const float* __restrict__ soff,
    float* __restrict__ stageRow, float* __restrict__ upPtr, int writeU)
{
    constexpr int NF = J0 + 4;
    float f[NF];
#pragma unroll
    for (int i = 0; i < NF / 4; i++) {
        float4 v = ((const float4*)fptr)[i];
        f[4*i] = v.x; f[4*i+1] = v.y; f[4*i+2] = v.z; f[4*i+3] = v.w;
    }
    if (writeU) {
        ((float4*)upPtr)[J0 / 4] =
            make_float4(f[J0]>0.f?1.f:0.f, f[J0+1]>0.f?1.f:0.f,
                        f[J0+2]>0.f?1.f:0.f, f[J0+3]>0.f?1.f:0.f);
    }
#pragma unroll
    for (int d = 0; d < D_; d++) {
        float off0 = (r > 0) ? soff[d * 64 + tr] : 0.f;
        float add0 = (r == 0) ? rnd9[d] : 0.f;
        float hd = (float)(d + 1);
        float acc = 0.f;
#pragma unroll
        for (int j = 0; j < J0; j++) {         // exact prefix fold
            float rad = rad_of(f[j], hd);
            if (j == 0) rad = __fadd_rn(rad, add0);
            acc = j ? __fadd_rn(acc, rad) : rad;
        }
#pragma unroll
        for (int j = J0; j < J0 + 4; j++) {
            float rad = rad_of(f[j], hd);
            if (j == 0) rad = __fadd_rn(rad, add0);
            acc = j ? __fadd_rn(acc, rad) : rad;
            float s  = __fadd_rn(off0, acc);
            float ph = __fmul_rn(s, 6.28318548202514648f);
            float sv = sin_ph2(s, ph);
            stageRow[j * 9 + d] = (f[j] > 0.f) ? __fmul_rn(sv, 0.1f) : 0.f;
        }
    }
}

// ---- kC: 256 threads = 64 rows x 4 quarters; S1 offsets coalesced via smem;
//          results staged in smem, coalesced float4 copy-out ----
__global__ void __launch_bounds__(256) kC(const float* __restrict__ f0,
                                          const float* __restrict__ rnd,
                                          float* __restrict__ outS,
                                          float* __restrict__ outU, int writeU) {
    __shared__ float soff[9 * 64];
    __shared__ float stage[64 * 145];
    int b  = blockIdx.y;
    int r0 = blockIdx.x * RPB;
    int nrows = min(RPB, NP1 - r0);
    int t = threadIdx.x;

    for (int i = t; i < 9 * 64; i += 256) {
        int d = i >> 6, k = i & 63;
        int rr = r0 - 1 + k;
        soff[i] = (rr >= 0 && k < nrows) ? g_S1[(size_t)(b * D_ + d) * NP1 + rr] : 0.f;
    }
    __syncthreads();

    int qk = t >> 6, tr = t & 63;
    if (tr < nrows) {
        int r = r0 + tr;
        const float* fptr = f0 + (size_t)b * L_ + (size_t)r * 16;
        float* upPtr = outU + (size_t)b * L_ + (size_t)r * 16;
        const float* rnd9 = rnd + b * D_;
        float* stageRow = stage + tr * 145;
        switch (qk) {
            case 0:  row_quarter<0>(fptr, rnd9, r, tr, soff, stageRow, upPtr, writeU); break;
            case 1:  row_quarter<4>(fptr, rnd9, r, tr, soff, stageRow, upPtr, writeU); break;
            case 2:  row_quarter<8>(fptr, rnd9, r, tr, soff, stageRow, upPtr, writeU); break;
            default: row_quarter<12>(fptr, rnd9, r, tr, soff, stageRow, upPtr, writeU); break;
        }
    }
    __syncthreads();

    int totw4 = nrows * 36;
    float4* og = (float4*)(outS + ((size_t)b * L_ + (size_t)r0 * 16) * D_);
    for (int w4 = t; w4 < totw4; w4 += 256) {
        int w = w4 << 2;
        int trr = w / 144, off = w - trr * 144;
        const float* s = stage + trr * 145 + off;
        og[w4] = make_float4(s[0], s[1], s[2], s[3]);
    }
}

extern "C" void kernel_launch(void* const* d_in, const int* in_sizes, int n_in,
                              void* d_out, int out_size) {
    const float* f0  = (const float*)d_in[0];
    const float* rnd = (const float*)d_in[1];
    float* outS = (float*)d_out;
    float* outU = outS + (size_t)B_ * L_ * D_;
    int writeU = (out_size >= B_ * L_ * D_ + B_ * L_) ? 1 : 0;

    kA<<<(B_ * NP1 + 255) / 256, 256>>>(f0, rnd);
    kB<<<B_ * D_, 512>>>();
    kB2<<<(B_ * D_ * NQ2 + 255) / 256, 256>>>();
    dim3 gc(NBX, B_);
    kC<<<gc, 256>>>(f0, rnd, outS, outU, writeU);
}

// round 17
// speedup vs baseline: 1.4636x; 1.0565x over previous
#include <cuda_runtime.h>

#define B_   16
#define L_   480000
#define D_   9
#define NP1  30000     // level-1 (16-sample rows)
#define NQ2  1875      // level-2
#define NU3  118       // level-3 (1875 padded to 1888)
#define NV4  8         // level-4 (118 padded to 128)
#define RPB  32
#define NBX  938       // ceil(30000/32)

__device__ float g_e1[B_ * D_ * NP1];
__device__ float g_S2[B_ * D_ * NQ2];
__device__ float g_S1[B_ * D_ * NP1];

// rad = fl( fl(f*h) * fl(1/24000) )  [XLA algsimp HandleDivide: A/c -> A*(1/c)]
#define RECIP_SR ((float)(1.0 / 24000.0))
__device__ __forceinline__ float rad_of(float f, float hd) {
    return __fmul_rn(__fmul_rn(f, hd), RECIP_SR);
}

__device__ __forceinline__ void load16(const float4* p, float x[16]) {
#pragma unroll
    for (int i = 0; i < 4; i++) {
        float4 v = p[i];
        x[4*i] = v.x; x[4*i+1] = v.y; x[4*i+2] = v.z; x[4*i+3] = v.w;
    }
}

// ---- kA: e1[p] = Seq16 of rads (rand_ini folded into element 0) ----
__global__ void __launch_bounds__(256) kA(const float* __restrict__ f0,
                                          const float* __restrict__ rnd) {
    int tid = blockIdx.x * 256 + threadIdx.x;
    if (tid >= B_ * NP1) return;
    int b = tid / NP1, p = tid - b * NP1;
    float f[16];
    load16((const float4*)(f0 + (size_t)b * L_ + (size_t)p * 16), f);
#pragma unroll
    for (int d = 0; d < D_; d++) {
        float hd = (float)(d + 1);
        float acc = 0.f;
#pragma unroll
        for (int j = 0; j < 16; j++) {
            float rad = rad_of(f[j], hd);
            if (p == 0 && j == 0) rad = __fadd_rn(rad, rnd[b * D_ + d]);
            acc = j ? __fadd_rn(acc, rad) : rad;
        }
        g_e1[(size_t)(b * D_ + d) * NP1 + p] = acc;
    }
}

// ---- kB: per (b,d) row -> S2 via e2,e3,e4,S4,S3 (all sequential) ----
__global__ void __launch_bounds__(512) kB() {
    __shared__ float e2[NQ2], e3[NU3], S3[NU3], S4[NV4];
    int row = blockIdx.x, t = threadIdx.x;
    const float* e1 = g_e1 + (size_t)row * NP1;
    for (int q = t; q < NQ2; q += 512) {
        float x[16];
        load16((const float4*)(e1 + q * 16), x);
        float acc = x[0];
#pragma unroll
        for (int j = 1; j < 16; j++) acc = __fadd_rn(acc, x[j]);
        e2[q] = acc;
    }
    __syncthreads();
    for (int u = t; u < NU3; u += 512) {
        int n = min(16, NQ2 - u * 16);
        float acc = 0.f;
        for (int j = 0; j < n; j++) {
            float v = e2[u * 16 + j];
            acc = j ? __fadd_rn(acc, v) : v;
        }
        e3[u] = acc;
    }
    __syncthreads();
    if (t == 0) {
        float e4[NV4];
        for (int v = 0; v < NV4; v++) {
            int n = min(16, NU3 - v * 16);
            float acc = 0.f;
            for (int j = 0; j < n; j++) {
                float x = e3[v * 16 + j];
                acc = j ? __fadd_rn(acc, x) : x;
            }
            e4[v] = acc;
        }
        float s = 0.f;
        for (int v = 0; v < NV4; v++) {
            s = v ? __fadd_rn(s, e4[v]) : e4[v];
            S4[v] = s;
        }
    }
    __syncthreads();
    for (int u = t; u < NU3; u += 512) {
        int base = (u >> 4) * 16;
        float off = (u >= 16) ? S4[(u >> 4) - 1] : 0.f;
        float acc = 0.f;
        for (int j = base; j <= u; j++)
            acc = (j == base) ? e3[j] : __fadd_rn(acc, e3[j]);
        S3[u] = __fadd_rn(off, acc);
    }
    __syncthreads();
    float* S2 = g_S2 + (size_t)row * NQ2;
    for (int q = t; q < NQ2; q += 512) {
        int base = (q >> 4) * 16;
        float off = (q >= 16) ? S3[(q >> 4) - 1] : 0.f;
        float acc = 0.f;
        for (int j = base; j <= q; j++)
            acc = (j == base) ? e2[j] : __fadd_rn(acc, e2[j]);
        S2[q] = __fadd_rn(off, acc);
    }
}

// ---- kB2: S1[p] = fadd(S2[q-1], seq-chain of e1 within 16-chunk) ----
__global__ void __launch_bounds__(256) kB2() {
    int tid = blockIdx.x * 256 + threadIdx.x;
    if (tid >= B_ * D_ * NQ2) return;
    int row = tid / NQ2, q = tid - row * NQ2;
    float off = q ? g_S2[(size_t)row * NQ2 + q - 1] : 0.f;
    float x[16];
    load16((const float4*)(g_e1 + (size_t)row * NP1 + (size_t)q * 16), x);
    float s[16];
    float acc = 0.f;
#pragma unroll
    for (int j = 0; j < 16; j++) {
        acc = j ? __fadd_rn(acc, x[j]) : x[j];
        s[j] = __fadd_rn(off, acc);
    }
    float4* o = (float4*)(g_S1 + (size_t)row * NP1 + (size_t)q * 16);
#pragma unroll
    for (int i = 0; i < 4; i++)
        o[i] = make_float4(s[4*i], s[4*i+1], s[4*i+2], s[4*i+3]);
}

__device__ __forceinline__ float sin_ph2(float s, float ph) {
    float k = rintf(s);                                  // valid reduction integer
    float r = __fmaf_rn(k, -6.28318548202514648f, ph);
    r       = __fmaf_rn(k, 1.7484556e-07f, r);
    return __sinf(r);
}

// one quarter of a row: recompute exact J0-prefix fold, emit samples J0..J0+3
template<int J0>
__device__ __forceinline__ void row_quarter(
    const float* __restrict__ fptr, const float* __restrict__ rnd9,
    int r, int tr, const float* __restrict__ soff,
    float* __restrict__ stageRow, float* __restrict__ upPtr, int writeU)
{
    constexpr int NF = J0 + 4;
    float f[NF];
#pragma unroll
    for (int i = 0; i < NF / 4; i++) {
        float4 v = ((const float4*)fptr)[i];
        f[4*i] = v.x; f[4*i+1] = v.y; f[4*i+2] = v.z; f[4*i+3] = v.w;
    }
    if (writeU) {
        ((float4*)upPtr)[J0 / 4] =
            make_float4(f[J0]>0.f?1.f:0.f, f[J0+1]>0.f?1.f:0.f,
                        f[J0+2]>0.f?1.f:0.f, f[J0+3]>0.f?1.f:0.f);
    }
#pragma unroll
    for (int d = 0; d < D_; d++) {
        float off0 = (r > 0) ? soff[d * RPB + tr] : 0.f;
        float add0 = (r == 0) ? rnd9[d] : 0.f;
        float hd = (float)(d + 1);
        float acc = 0.f;
#pragma unroll
        for (int j = 0; j < J0; j++) {         // exact prefix fold
            float rad = rad_of(f[j], hd);
            if (j == 0) rad = __fadd_rn(rad, add0);
            acc = j ? __fadd_rn(acc, rad) : rad;
        }
#pragma unroll
        for (int j = J0; j < J0 + 4; j++) {
            float rad = rad_of(f[j], hd);
            if (j == 0) rad = __fadd_rn(rad, add0);
            acc = j ? __fadd_rn(acc, rad) : rad;
            float s  = __fadd_rn(off0, acc);
            float ph = __fmul_rn(s, 6.28318548202514648f);
            float sv = sin_ph2(s, ph);
            stageRow[j * 9 + d] = (f[j] > 0.f) ? __fmul_rn(sv, 0.1f) : 0.f;
        }
    }
}

// ---- kC: 128 threads = 32 rows x 4 quarters; 11 blocks/SM target ----
__global__ void __launch_bounds__(128, 11) kC(const float* __restrict__ f0,
                                              const float* __restrict__ rnd,
                                              float* __restrict__ outS,
                                              float* __restrict__ outU, int writeU) {
    __shared__ float soff[9 * RPB];
    __shared__ float stage[RPB * 145];
    int b  = blockIdx.y;
    int r0 = blockIdx.x * RPB;
    int nrows = min(RPB, NP1 - r0);
    int t = threadIdx.x;

    for (int i = t; i < 9 * RPB; i += 128) {
        int d = i >> 5, k = i & 31;
        int rr = r0 - 1 + k;
        soff[i] = (rr >= 0 && k < nrows) ? g_S1[(size_t)(b * D_ + d) * NP1 + rr] : 0.f;
    }
    __syncthreads();

    int qk = t >> 5, tr = t & 31;            // warp-uniform quarter
    if (tr < nrows) {
        int r = r0 + tr;
        const float* fptr = f0 + (size_t)b * L_ + (size_t)r * 16;
        float* upPtr = outU + (size_t)b * L_ + (size_t)r * 16;
        const float* rnd9 = rnd + b * D_;
        float* stageRow = stage + tr * 145;
        switch (qk) {
            case 0:  row_quarter<0>(fptr, rnd9, r, tr, soff, stageRow, upPtr, writeU); break;
            case 1:  row_quarter<4>(fptr, rnd9, r, tr, soff, stageRow, upPtr, writeU); break;
            case 2:  row_quarter<8>(fptr, rnd9, r, tr, soff, stageRow, upPtr, writeU); break;
            default: row_quarter<12>(fptr, rnd9, r, tr, soff, stageRow, upPtr, writeU); break;
        }
    }
    __syncthreads();

    int totw4 = nrows * 36;
    float4* og = (float4*)(outS + ((size_t)b * L_ + (size_t)r0 * 16) * D_);
    for (int w4 = t; w4 < totw4; w4 += 128) {
        int w = w4 << 2;
        int trr = w / 144, off = w - trr * 144;
        const float* s = stage + trr * 145 + off;
        og[w4] = make_float4(s[0], s[1], s[2], s[3]);
    }
}

extern "C" void kernel_launch(void* const* d_in, const int* in_sizes, int n_in,
                              void* d_out, int out_size) {
    const float* f0  = (const float*)d_in[0];
    const float* rnd = (const float*)d_in[1];
    float* outS = (float*)d_out;
    float* outU = outS + (size_t)B_ * L_ * D_;
    int writeU = (out_size >= B_ * L_ * D_ + B_ * L_) ? 1 : 0;

    kA<<<(B_ * NP1 + 255) / 256, 256>>>(f0, rnd);
    kB<<<B_ * D_, 512>>>();
    kB2<<<(B_ * D_ * NQ2 + 255) / 256, 256>>>();
    dim3 gc(NBX, B_);
    kC<<<gc, 128>>>(f0, rnd, outS, outU, writeU);
}